// round 17
// baseline (speedup 1.0000x reference)
#include <cuda_runtime.h>
#include <cuda_bf16.h>
#include <stdint.h>

// ---------------- problem constants ----------------
#define E_TOTAL   1600000
#define N_NODES   100000
#define NODE_DIM  64
#define EDGE_DIM  32
#define HID       128
#define OUT_DIM   64
#define HPRE_DIM  256          // [src-part 128 | tgt-part 128]

#define TPW       16           // edges per warp-tile (one m16 MMA tile)
#define NTILES16  (E_TOTAL / TPW)   // 100000
#define NT2       448
#define NW2       14

// ---------------- kernel2 smem layout (word = u32, bf16x2 over k) ----------------
#define W1ROW     20           // [128 j][16 w] + 4 pad; banks 20g+tg distinct mod 32
#define EAROW     20           // [16 e][16 w] + 4 pad
#define ROWW      68           // [16 e][64 w] + 4 pad (layer-2 A / h)
#define SO_W1PH   0                          // 128*20*4 = 10240
#define SO_W1PL   10240                      // 10240
#define SO_W2PH   20480                      // 64*68*4 = 17408
#define SO_W2PL   37888                      // 17408
#define SO_EAH    55296                      // 14 w x 16*20*4 = 17920
#define SO_EAL    73216                      // 17920
#define SO_HPH    91136                      // 14 w x 16*68*4 = 60928
#define SO_HPL    152064                     // 60928
#define SO_B1     212992                     // 128 f32 = 512
#define SO_B2     213504                     // 256
#define SM2_BYTES 213760

typedef unsigned long long u64;

__device__ __forceinline__ u64 fma2(u64 a, u64 b, u64 c) {
    u64 d; asm("fma.rn.f32x2 %0, %1, %2, %3;" : "=l"(d) : "l"(a), "l"(b), "l"(c)); return d;
}
__device__ __forceinline__ u64 pack2(float lo, float hi) {
    u64 d; asm("mov.b64 %0, {%1, %2};" : "=l"(d) : "f"(lo), "f"(hi)); return d;
}
// packed bf16x2: lower half <- lo_f32, upper half <- hi_f32
__device__ __forceinline__ uint32_t packbf2(float lo, float hi) {
    uint32_t d; asm("cvt.rn.bf16x2.f32 %0, %1, %2;" : "=r"(d) : "f"(hi), "f"(lo)); return d;
}
__device__ __forceinline__ float bf_lo(uint32_t p) { return __uint_as_float(p << 16); }
__device__ __forceinline__ float bf_hi(uint32_t p) { return __uint_as_float(p & 0xffff0000u); }

__device__ __forceinline__ void mma_bf16(float* c, const uint32_t* a, const uint32_t* b) {
    asm("mma.sync.aligned.m16n8k16.row.col.f32.bf16.bf16.f32 "
        "{%0,%1,%2,%3}, {%4,%5,%6,%7}, {%8,%9}, {%0,%1,%2,%3};"
        : "+f"(c[0]), "+f"(c[1]), "+f"(c[2]), "+f"(c[3])
        : "r"(a[0]), "r"(a[1]), "r"(a[2]), "r"(a[3]), "r"(b[0]), "r"(b[1]));
}

// Per-node precomputed partials:
// [n][0:128] = x[n] @ W1[0:64,:], [n][128:256] = x[n] @ W1[64:128,:]
__device__ float g_hpre[(size_t)N_NODES * HPRE_DIM];
__device__ int g_idx_is32;

__global__ void detect_idx_dtype_kernel(const unsigned int* __restrict__ a) {
    unsigned v = 0;
    for (int i = threadIdx.x; i < 2048; i += blockDim.x) v |= a[2 * i + 1];
    int any = __syncthreads_or(v != 0);
    if (threadIdx.x == 0) g_idx_is32 = any ? 1 : 0;
}

// ---------------- kernel 1: per-node precompute (unchanged, proven) ----------------
__global__ void __launch_bounds__(256, 1)
node_pre_kernel(const float* __restrict__ x, const float* __restrict__ W1)
{
    __shared__ float Wc[64 * 256];
    const int tid = threadIdx.x;
    for (int i = tid; i < 64 * 256; i += 256) {
        int k = i >> 8, j = i & 255;
        Wc[i] = (j < 128) ? W1[k * HID + j] : W1[(64 + k) * HID + (j - 128)];
    }
    __syncthreads();

    const int warp = tid >> 5, lane = tid & 31;
    const int gw = blockIdx.x * 8 + warp;
    const int nw = gridDim.x * 8;

    for (int n = gw; n < N_NODES; n += nw) {
        u64 acc0 = 0, acc1 = 0, acc2 = 0, acc3 = 0;
        const float4* xr = (const float4*)(x + (size_t)n * NODE_DIM);
#pragma unroll 4
        for (int c = 0; c < 16; c++) {
            float4 m = xr[c];
            float mv[4] = {m.x, m.y, m.z, m.w};
#pragma unroll
            for (int k = 0; k < 4; k++) {
                int kk = 4 * c + k;
                ulonglong2 w0 = *(const ulonglong2*)(Wc + kk * 256 + 4 * lane);
                ulonglong2 w1 = *(const ulonglong2*)(Wc + kk * 256 + 128 + 4 * lane);
                u64 pk = pack2(mv[k], mv[k]);
                acc0 = fma2(pk, w0.x, acc0);
                acc1 = fma2(pk, w0.y, acc1);
                acc2 = fma2(pk, w1.x, acc2);
                acc3 = fma2(pk, w1.y, acc3);
            }
        }
        ulonglong2 s0; s0.x = acc0; s0.y = acc1;
        ulonglong2 s1; s1.x = acc2; s1.y = acc3;
        *(ulonglong2*)(g_hpre + (size_t)n * HPRE_DIM + 4 * lane) = s0;
        *(ulonglong2*)(g_hpre + (size_t)n * HPRE_DIM + 128 + 4 * lane) = s1;
    }
}

// ---------------- kernel 2: both layers on split-bf16 HMMA ----------------
__global__ void __launch_bounds__(NT2, 1)
edge_kernel(const float* __restrict__ ea,
            const float* __restrict__ W1,
            const float* __restrict__ b1,
            const float* __restrict__ W2,
            const float* __restrict__ b2,
            const void*  __restrict__ eidx,
            float* __restrict__ out)
{
    extern __shared__ __align__(1024) char smem[];
    uint32_t* W1ph = (uint32_t*)(smem + SO_W1PH);  // [128 j][20]
    uint32_t* W1pl = (uint32_t*)(smem + SO_W1PL);
    uint32_t* W2ph = (uint32_t*)(smem + SO_W2PH);  // [64 n][68]
    uint32_t* W2pl = (uint32_t*)(smem + SO_W2PL);
    float*    b1s  = (float*)(smem + SO_B1);
    float*    b2s  = (float*)(smem + SO_B2);

    const int tid  = threadIdx.x;
    const int warp = tid >> 5;
    const int lane = tid & 31;
    const int g    = lane >> 2;       // MMA group id 0..7
    const int tg   = lane & 3;        // MMA thread-in-group 0..3

    uint32_t* eah = (uint32_t*)(smem + SO_EAH) + warp * (TPW * EAROW);   // [16 e][20]
    uint32_t* eal = (uint32_t*)(smem + SO_EAL) + warp * (TPW * EAROW);
    uint32_t* hph = (uint32_t*)(smem + SO_HPH) + warp * (TPW * ROWW);    // [16 e][68]
    uint32_t* hpl = (uint32_t*)(smem + SO_HPL) + warp * (TPW * ROWW);

    // ---- stage W1 rows 128..159 as bf16x2-over-k hi/lo: W1p[j][w] = (W1[128+2w][j], W1[128+2w+1][j]) ----
    for (int i = tid; i < HID * (EDGE_DIM / 2); i += NT2) {
        int j = i >> 4, w = i & 15;
        float f0 = W1[(128 + 2 * w) * HID + j];
        float f1 = W1[(128 + 2 * w + 1) * HID + j];
        uint32_t hi = packbf2(f0, f1);
        W1ph[j * W1ROW + w] = hi;
        W1pl[j * W1ROW + w] = packbf2(f0 - bf_lo(hi), f1 - bf_hi(hi));
    }
    // ---- stage W2 as bf16x2-over-k hi/lo: W2p[n][w] = (W2[2w][n], W2[2w+1][n]) ----
    for (int i = tid; i < OUT_DIM * (HID / 2); i += NT2) {
        int n = i >> 6, w = i & 63;
        float f0 = W2[(2 * w) * OUT_DIM + n];
        float f1 = W2[(2 * w + 1) * OUT_DIM + n];
        uint32_t hi = packbf2(f0, f1);
        W2ph[n * ROWW + w] = hi;
        W2pl[n * ROWW + w] = packbf2(f0 - bf_lo(hi), f1 - bf_hi(hi));
    }
    for (int i = tid; i < HID; i += NT2) b1s[i] = b1[i];
    for (int i = tid; i < OUT_DIM; i += NT2) b2s[i] = b2[i];
    __syncthreads();

    const int is32 = g_idx_is32;
    const int* e32 = (const int*)eidx;
    const long long* e64 = (const long long*)eidx;

    const int gwarp = blockIdx.x * NW2 + warp;
    const int wstride = gridDim.x * NW2;

    for (int t = gwarp; t < NTILES16; t += wstride) {
        const int ebase = t * TPW;

        // ---- edge indices for 16 edges: lanes 0..15 load, shfl rows g and g+8 ----
        int sv = 0, tv = 0;
        if (lane < TPW) {
            int e = ebase + lane;
            if (is32) { sv = e32[e]; tv = e32[E_TOTAL + e]; }
            else      { sv = (int)e64[e]; tv = (int)e64[E_TOTAL + e]; }
        }
        const int se0 = __shfl_sync(0xffffffffu, sv, g);
        const int se1 = __shfl_sync(0xffffffffu, sv, g + 8);
        const int te0 = __shfl_sync(0xffffffffu, tv, g);
        const int te1 = __shfl_sync(0xffffffffu, tv, g + 8);

        // ---- stage edge_attr as bf16 hi/lo A-tile: 128 float4, 4 per lane ----
#pragma unroll
        for (int p = 0; p < 4; p++) {
            int i = lane + 32 * p;
            int e = i >> 3, q = i & 7;                 // q-th float4 of row e (k=4q..4q+3)
            float4 v = *(const float4*)(ea + (size_t)(ebase + e) * EDGE_DIM + 4 * q);
            uint32_t h0 = packbf2(v.x, v.y);
            uint32_t h1 = packbf2(v.z, v.w);
            uint32_t l0 = packbf2(v.x - bf_lo(h0), v.y - bf_hi(h0));
            uint32_t l1 = packbf2(v.z - bf_lo(h1), v.w - bf_hi(h1));
            *(u64*)(eah + e * EAROW + 2 * q) = ((u64)h1 << 32) | h0;
            *(u64*)(eal + e * EAROW + 2 * q) = ((u64)l1 << 32) | l0;
        }
        __syncwarp();

        // ---- layer-1 A fragments (kept across both halves): kt 0,1 ----
        uint32_t a1h[8], a1l[8];
#pragma unroll
        for (int kt = 0; kt < 2; kt++) {
            const int wb = kt * 8 + tg;
            a1h[kt * 4 + 0] = eah[g * EAROW + wb];
            a1h[kt * 4 + 1] = eah[(g + 8) * EAROW + wb];
            a1h[kt * 4 + 2] = eah[g * EAROW + wb + 4];
            a1h[kt * 4 + 3] = eah[(g + 8) * EAROW + wb + 4];
            a1l[kt * 4 + 0] = eal[g * EAROW + wb];
            a1l[kt * 4 + 1] = eal[(g + 8) * EAROW + wb];
            a1l[kt * 4 + 2] = eal[g * EAROW + wb + 4];
            a1l[kt * 4 + 3] = eal[(g + 8) * EAROW + wb + 4];
        }

        // ---- layer 1: two 64-column halves ----
#pragma unroll
        for (int half = 0; half < 2; half++) {
            float acc1[8][4];
#pragma unroll
            for (int n0 = 0; n0 < 8; n0++)
#pragma unroll
                for (int r = 0; r < 4; r++) acc1[n0][r] = 0.0f;

#pragma unroll
            for (int n0 = 0; n0 < 8; n0++) {
                const int n = half * 64 + n0 * 8 + g;
#pragma unroll
                for (int kt = 0; kt < 2; kt++) {
                    const int wb = kt * 8 + tg;
                    uint32_t bh[2], bl[2];
                    bh[0] = W1ph[n * W1ROW + wb];
                    bh[1] = W1ph[n * W1ROW + wb + 4];
                    bl[0] = W1pl[n * W1ROW + wb];
                    bl[1] = W1pl[n * W1ROW + wb + 4];
                    mma_bf16(acc1[n0], a1h + kt * 4, bh);
                    mma_bf16(acc1[n0], a1h + kt * 4, bl);
                    mma_bf16(acc1[n0], a1l + kt * 4, bh);
                }
            }

            // ---- epilogue: + b1 + hpre_src + hpre_tgt, relu, bf16 hi/lo split to hph/hpl ----
#pragma unroll
            for (int n0 = 0; n0 < 8; n0++) {
                const int C = half * 64 + n0 * 8 + 2 * tg;     // even column pair
                float2 bb  = *(const float2*)(b1s + C);
                float2 hs0 = *(const float2*)(g_hpre + (size_t)se0 * HPRE_DIM + C);
                float2 hs1 = *(const float2*)(g_hpre + (size_t)se1 * HPRE_DIM + C);
                float2 ht0 = *(const float2*)(g_hpre + (size_t)te0 * HPRE_DIM + 128 + C);
                float2 ht1 = *(const float2*)(g_hpre + (size_t)te1 * HPRE_DIM + 128 + C);
                float v0 = fmaxf(acc1[n0][0] + bb.x + hs0.x + ht0.x, 0.0f);
                float v1 = fmaxf(acc1[n0][1] + bb.y + hs0.y + ht0.y, 0.0f);
                float v2 = fmaxf(acc1[n0][2] + bb.x + hs1.x + ht1.x, 0.0f);
                float v3 = fmaxf(acc1[n0][3] + bb.y + hs1.y + ht1.y, 0.0f);
                const int w = C >> 1;                          // k-word index
                uint32_t h0 = packbf2(v0, v1);
                uint32_t h1 = packbf2(v2, v3);
                hph[g * ROWW + w]       = h0;
                hph[(g + 8) * ROWW + w] = h1;
                hpl[g * ROWW + w]       = packbf2(v0 - bf_lo(h0), v1 - bf_hi(h0));
                hpl[(g + 8) * ROWW + w] = packbf2(v2 - bf_lo(h1), v3 - bf_hi(h1));
            }
        }
        __syncwarp();

        // ---- layer 2: m16n8k16 bf16 MMA, 3-term split (validated R16 form) ----
        float acc2[8][4];
#pragma unroll
        for (int n0 = 0; n0 < 8; n0++)
#pragma unroll
            for (int r = 0; r < 4; r++) acc2[n0][r] = 0.0f;

#pragma unroll
        for (int kt = 0; kt < 8; kt++) {               // 8 k-tiles of 16
            const int wb = kt * 8 + tg;
            uint32_t ahi[4], alo[4];
            ahi[0] = hph[g * ROWW + wb];
            ahi[1] = hph[(g + 8) * ROWW + wb];
            ahi[2] = hph[g * ROWW + wb + 4];
            ahi[3] = hph[(g + 8) * ROWW + wb + 4];
            alo[0] = hpl[g * ROWW + wb];
            alo[1] = hpl[(g + 8) * ROWW + wb];
            alo[2] = hpl[g * ROWW + wb + 4];
            alo[3] = hpl[(g + 8) * ROWW + wb + 4];
#pragma unroll
            for (int n0 = 0; n0 < 8; n0++) {
                uint32_t bh[2], bl[2];
                bh[0] = W2ph[(n0 * 8 + g) * ROWW + wb];
                bh[1] = W2ph[(n0 * 8 + g) * ROWW + wb + 4];
                bl[0] = W2pl[(n0 * 8 + g) * ROWW + wb];
                bl[1] = W2pl[(n0 * 8 + g) * ROWW + wb + 4];
                mma_bf16(acc2[n0], ahi, bh);
                mma_bf16(acc2[n0], ahi, bl);
                mma_bf16(acc2[n0], alo, bh);
            }
        }

        // ---- epilogue: bias + stores ----
#pragma unroll
        for (int n0 = 0; n0 < 8; n0++) {
            int col = n0 * 8 + 2 * tg;
            float2 bb = *(const float2*)(b2s + col);
            float2 v0, v1;
            v0.x = acc2[n0][0] + bb.x; v0.y = acc2[n0][1] + bb.y;
            v1.x = acc2[n0][2] + bb.x; v1.y = acc2[n0][3] + bb.y;
            *(float2*)(out + (size_t)(ebase + g) * OUT_DIM + col) = v0;
            *(float2*)(out + (size_t)(ebase + g + 8) * OUT_DIM + col) = v1;
        }
        __syncwarp();   // before eah/eal/hph/hpl reuse next tile
    }
}

extern "C" void kernel_launch(void* const* d_in, const int* in_sizes, int n_in,
                              void* d_out, int out_size)
{
    const float* x  = (const float*)d_in[0];
    const float* ea = (const float*)d_in[1];
    const float* W1 = (const float*)d_in[2];
    const float* b1 = (const float*)d_in[3];
    const float* W2 = (const float*)d_in[4];
    const float* b2 = (const float*)d_in[5];
    const void*  ei = d_in[6];
    float* out = (float*)d_out;

    cudaFuncSetAttribute(edge_kernel,
                         cudaFuncAttributeMaxDynamicSharedMemorySize, SM2_BYTES);

    detect_idx_dtype_kernel<<<1, 256>>>((const unsigned int*)ei);
    node_pre_kernel<<<1480, 256>>>(x, W1);
    edge_kernel<<<1480, NT2, SM2_BYTES>>>(ea, W1, b1, W2, b2, ei, out);
}